// round 4
// baseline (speedup 1.0000x reference)
#include <cuda_runtime.h>
#include <cuda_bf16.h>
#include <cstdint>

#define T_DIM 32
#define WAY 64
#define SHOT 8
#define QUERY 16
#define C_DIM 1024
#define WQ (WAY * QUERY)   // 1024

#define BM 128
#define BK 16
#define NK (C_DIM / BK)    // 64 k-chunks
#define NSTG 3             // cp.async pipeline depth
#define QSTRIDE 20         // f32 words per smem row: (20*r + k) % 32 injective -> conflict-free
#define QSTG (BM * QSTRIDE)    // 2560 f32
#define PSTG (WAY * QSTRIDE)   // 1280 f32

// Scratch (no allocations allowed): proto f32 (8 MB) + ||p||^2 fp32.
__device__ float g_proto[T_DIM * WAY * C_DIM];
__device__ float g_psq[T_DIM * WAY];

// ---------------------------------------------------------------------------
// Kernel 1: prototypes (mean over shots) -> f32, and p_sq
// grid (WAY, T), 256 threads; each thread owns 4 contiguous columns.
// ---------------------------------------------------------------------------
__global__ __launch_bounds__(256) void proto_kernel(const float* __restrict__ support) {
    const int way = blockIdx.x;
    const int t   = blockIdx.y;
    const int tid = threadIdx.x;

    const float* base = support + ((size_t)t * WAY * SHOT + (size_t)way * SHOT) * C_DIM + tid * 4;

    float4 s = make_float4(0.f, 0.f, 0.f, 0.f);
#pragma unroll
    for (int sh = 0; sh < SHOT; sh++) {
        float4 v = *(const float4*)(base + (size_t)sh * C_DIM);
        s.x += v.x; s.y += v.y; s.z += v.z; s.w += v.w;
    }
    s.x *= 0.125f; s.y *= 0.125f; s.z *= 0.125f; s.w *= 0.125f;

    *(float4*)&g_proto[((size_t)(t * WAY + way)) * C_DIM + tid * 4] = s;

    float ss = s.x * s.x + s.y * s.y + s.z * s.z + s.w * s.w;
#pragma unroll
    for (int off = 16; off > 0; off >>= 1)
        ss += __shfl_xor_sync(0xffffffffu, ss, off);

    __shared__ float red[8];
    if ((tid & 31) == 0) red[tid >> 5] = ss;
    __syncthreads();
    if (tid == 0) {
        float tot = 0.f;
#pragma unroll
        for (int w = 0; w < 8; w++) tot += red[w];
        g_psq[t * WAY + way] = tot;
    }
}

// ---------------------------------------------------------------------------
// tf32 mma m16n8k8 (f32 operands passed through; HW truncates to tf32)
// ---------------------------------------------------------------------------
__device__ __forceinline__ void mma_tf32(float* d, const float* a, const float* b) {
    asm volatile(
        "mma.sync.aligned.m16n8k8.row.col.f32.tf32.tf32.f32 "
        "{%0,%1,%2,%3}, {%4,%5,%6,%7}, {%8,%9}, {%0,%1,%2,%3};\n"
        : "+f"(d[0]), "+f"(d[1]), "+f"(d[2]), "+f"(d[3])
        : "r"(__float_as_uint(a[0])), "r"(__float_as_uint(a[1])),
          "r"(__float_as_uint(a[2])), "r"(__float_as_uint(a[3])),
          "r"(__float_as_uint(b[0])), "r"(__float_as_uint(b[1])));
}

__device__ __forceinline__ void cp_async16(uint32_t smem_addr, const void* gptr) {
    asm volatile("cp.async.cg.shared.global [%0], [%1], 16;\n"
                 :: "r"(smem_addr), "l"(gptr));
}
__device__ __forceinline__ void cp_commit() {
    asm volatile("cp.async.commit_group;\n");
}
__device__ __forceinline__ void cp_wait1() {
    asm volatile("cp.async.wait_group 1;\n");
}

// ---------------------------------------------------------------------------
// Kernel 2: fused GEMM + norms + epilogue, 3-stage cp.async pipeline.
// grid (8, T). 256 threads = 8 warps (4 M-strips x 2 N-strips of 32x32).
// dist = 2*qp - q_sq - p_sq
// ---------------------------------------------------------------------------
__global__ __launch_bounds__(256, 2) void dist_kernel(const float* __restrict__ query,
                                                      float* __restrict__ out) {
    const int t    = blockIdx.y;
    const int rb   = blockIdx.x;
    const int tid  = threadIdx.x;
    const int lane = tid & 31;
    const int warp = tid >> 5;
    const int warpM = warp & 3;   // 0..3
    const int warpN = warp >> 2;  // 0..1

    __shared__ __align__(16) float sQ[NSTG * QSTG];
    __shared__ __align__(16) float sP[NSTG * PSTG];
    __shared__ float sQsq[BM];
    __shared__ float sPsq[WAY];

    if (tid < WAY) sPsq[tid] = g_psq[t * WAY + tid];

    const float* qbase = query + ((size_t)t * WQ + (size_t)rb * BM) * C_DIM;
    const float* pbase = g_proto + (size_t)t * WAY * C_DIM;

    // cp.async mappings: Q: 2 threads/row x 8 floats; P: 4 threads/row x 4 floats
    const int qrow = tid >> 1, qoff = (tid & 1) * 8;
    const int prow = tid >> 2, poff = (tid & 3) * 4;
    const uint32_t sQb = (uint32_t)__cvta_generic_to_shared(&sQ[0]);
    const uint32_t sPb = (uint32_t)__cvta_generic_to_shared(&sP[0]);
    const uint32_t qdst = sQb + (uint32_t)(qrow * QSTRIDE + qoff) * 4u;
    const uint32_t pdst = sPb + (uint32_t)(prow * QSTRIDE + poff) * 4u;
    const float* qsrc = qbase + (size_t)qrow * C_DIM + qoff;
    const float* psrc = pbase + (size_t)prow * C_DIM + poff;

    float acc[2][4][4];
    float qsq[2][2];
#pragma unroll
    for (int mt = 0; mt < 2; mt++) {
        qsq[mt][0] = 0.f; qsq[mt][1] = 0.f;
#pragma unroll
        for (int nt = 0; nt < 4; nt++)
#pragma unroll
            for (int i = 0; i < 4; i++) acc[mt][nt][i] = 0.f;
    }

    // prologue: issue stages 0,1
#pragma unroll
    for (int s = 0; s < NSTG - 1; s++) {
        const uint32_t qd = qdst + (uint32_t)(s * QSTG) * 4u;
        const float*   qg = qsrc + s * BK;
        cp_async16(qd, qg);
        cp_async16(qd + 16u, qg + 4);
        cp_async16(pdst + (uint32_t)(s * PSTG) * 4u, psrc + s * BK);
        cp_commit();
    }

    int st = 0;
    for (int kk = 0; kk < NK; kk++) {
        cp_wait1();          // stage `st` data arrived
        __syncthreads();     // and everyone is done computing stage (st-1)

        // issue stage kk+2 into buffer (st+2)%3 (that's the one freed last iter)
        if (kk + (NSTG - 1) < NK) {
            int s2 = st + (NSTG - 1); if (s2 >= NSTG) s2 -= NSTG;
            const uint32_t qd = qdst + (uint32_t)(s2 * QSTG) * 4u;
            const float*   qg = qsrc + (kk + NSTG - 1) * BK;
            cp_async16(qd, qg);
            cp_async16(qd + 16u, qg + 4);
            cp_async16(pdst + (uint32_t)(s2 * PSTG) * 4u, psrc + (kk + NSTG - 1) * BK);
        }
        cp_commit();         // commit every iter (possibly empty) to keep group count uniform

        const float* Qs = sQ + st * QSTG;
        const float* Ps = sP + st * PSTG;

#pragma unroll
        for (int ks = 0; ks < 2; ks++) {
            const int kb = ks * 8 + (lane & 3);
            float a[2][4], b[4][2];
#pragma unroll
            for (int mt = 0; mt < 2; mt++) {
                const int r = warpM * 32 + mt * 16 + (lane >> 2);
                a[mt][0] = Qs[r * QSTRIDE + kb];
                a[mt][1] = Qs[(r + 8) * QSTRIDE + kb];
                a[mt][2] = Qs[r * QSTRIDE + kb + 4];
                a[mt][3] = Qs[(r + 8) * QSTRIDE + kb + 4];
            }
            if (warpN == 0) {   // warp-uniform: only N-strip 0 accumulates q^2
#pragma unroll
                for (int mt = 0; mt < 2; mt++) {
                    qsq[mt][0] += a[mt][0] * a[mt][0] + a[mt][2] * a[mt][2];
                    qsq[mt][1] += a[mt][1] * a[mt][1] + a[mt][3] * a[mt][3];
                }
            }
#pragma unroll
            for (int nt = 0; nt < 4; nt++) {
                const int n = warpN * 32 + nt * 8 + (lane >> 2);
                b[nt][0] = Ps[n * QSTRIDE + kb];
                b[nt][1] = Ps[n * QSTRIDE + kb + 4];
            }
#pragma unroll
            for (int mt = 0; mt < 2; mt++)
#pragma unroll
                for (int nt = 0; nt < 4; nt++)
                    mma_tf32(acc[mt][nt], a[mt], b[nt]);
        }

        st++; if (st == NSTG) st = 0;
    }

    // ---- q^2: reduce quad partials (k-lanes) and publish ----
    if (warpN == 0) {
#pragma unroll
        for (int mt = 0; mt < 2; mt++)
#pragma unroll
            for (int h = 0; h < 2; h++) {
                float v = qsq[mt][h];
                v += __shfl_xor_sync(0xffffffffu, v, 1);
                v += __shfl_xor_sync(0xffffffffu, v, 2);
                if ((lane & 3) == 0)
                    sQsq[warpM * 32 + mt * 16 + h * 8 + (lane >> 2)] = v;
            }
    }
    __syncthreads();

    // ---- epilogue: dist = 2*qp - q_sq - p_sq ----
    float* obase = out + ((size_t)t * WQ + (size_t)rb * BM) * WAY;
#pragma unroll
    for (int mt = 0; mt < 2; mt++) {
        const int r0 = warpM * 32 + mt * 16 + (lane >> 2);
        const float qs0 = sQsq[r0];
        const float qs1 = sQsq[r0 + 8];
#pragma unroll
        for (int nt = 0; nt < 4; nt++) {
            const int c0 = warpN * 32 + nt * 8 + (lane & 3) * 2;
            const float ps0 = sPsq[c0];
            const float ps1 = sPsq[c0 + 1];
            float2 d0, d1;
            d0.x = 2.f * acc[mt][nt][0] - qs0 - ps0;
            d0.y = 2.f * acc[mt][nt][1] - qs0 - ps1;
            d1.x = 2.f * acc[mt][nt][2] - qs1 - ps0;
            d1.y = 2.f * acc[mt][nt][3] - qs1 - ps1;
            *(float2*)(obase + (size_t)r0 * WAY + c0) = d0;
            *(float2*)(obase + (size_t)(r0 + 8) * WAY + c0) = d1;
        }
    }
}

extern "C" void kernel_launch(void* const* d_in, const int* in_sizes, int n_in,
                              void* d_out, int out_size) {
    const float* query   = (const float*)d_in[0];   // [32, 1024, 1024]
    const float* support = (const float*)d_in[1];   // [32, 512, 1024]
    float* out = (float*)d_out;                     // [32, 1024, 64]

    proto_kernel<<<dim3(WAY, T_DIM), 256>>>(support);
    dist_kernel<<<dim3(WQ / BM, T_DIM), 256>>>(query, out);
}

// round 11
// speedup vs baseline: 1.0968x; 1.0968x over previous
#include <cuda_runtime.h>
#include <cuda_bf16.h>
#include <cstdint>

#define T_DIM 32
#define WAY 64
#define SHOT 8
#define QUERY 16
#define C_DIM 1024
#define WQ (WAY * QUERY)   // 1024

#define BM 64
#define BK 64
#define NK (C_DIM / BK)    // 16
#define LDS_Q 72           // padded stride (bf16): 36 banks -> conflict-free frags
#define LDS_P 72

// Scratch (no allocations allowed): proto bf16 (4 MB) + ||p||^2 fp32.
__device__ __nv_bfloat16 g_proto[T_DIM * WAY * C_DIM];
__device__ float g_psq[T_DIM * WAY];

// ---------------------------------------------------------------------------
// Kernel 1: prototypes (mean over shots) -> bf16, and p_sq (fp32 means)
// grid (WAY, T), 256 threads; each thread owns 4 contiguous columns.
// ---------------------------------------------------------------------------
__global__ __launch_bounds__(256) void proto_kernel(const float* __restrict__ support) {
    const int way = blockIdx.x;
    const int t   = blockIdx.y;
    const int tid = threadIdx.x;

    const float* base = support + ((size_t)t * WAY * SHOT + (size_t)way * SHOT) * C_DIM + tid * 4;

    float4 s = make_float4(0.f, 0.f, 0.f, 0.f);
#pragma unroll
    for (int sh = 0; sh < SHOT; sh++) {
        float4 v = *(const float4*)(base + (size_t)sh * C_DIM);
        s.x += v.x; s.y += v.y; s.z += v.z; s.w += v.w;
    }
    s.x *= 0.125f; s.y *= 0.125f; s.z *= 0.125f; s.w *= 0.125f;

    __nv_bfloat162 lo = __floats2bfloat162_rn(s.x, s.y);
    __nv_bfloat162 hi = __floats2bfloat162_rn(s.z, s.w);
    uint2 packed;
    packed.x = *(const uint32_t*)&lo;
    packed.y = *(const uint32_t*)&hi;
    *(uint2*)&g_proto[((size_t)(t * WAY + way)) * C_DIM + tid * 4] = packed;

    float ss = s.x * s.x + s.y * s.y + s.z * s.z + s.w * s.w;
#pragma unroll
    for (int off = 16; off > 0; off >>= 1)
        ss += __shfl_xor_sync(0xffffffffu, ss, off);

    __shared__ float red[8];
    if ((tid & 31) == 0) red[tid >> 5] = ss;
    __syncthreads();
    if (tid == 0) {
        float tot = 0.f;
#pragma unroll
        for (int w = 0; w < 8; w++) tot += red[w];
        g_psq[t * WAY + way] = tot;
    }
}

// ---------------------------------------------------------------------------
// mma.sync m16n8k16 bf16 -> f32
// ---------------------------------------------------------------------------
__device__ __forceinline__ void mma16816(float* d, const uint32_t* a, const uint32_t* b) {
    asm volatile(
        "mma.sync.aligned.m16n8k16.row.col.f32.bf16.bf16.f32 "
        "{%0,%1,%2,%3}, {%4,%5,%6,%7}, {%8,%9}, {%0,%1,%2,%3};\n"
        : "+f"(d[0]), "+f"(d[1]), "+f"(d[2]), "+f"(d[3])
        : "r"(a[0]), "r"(a[1]), "r"(a[2]), "r"(a[3]), "r"(b[0]), "r"(b[1]));
}

// ---------------------------------------------------------------------------
// Kernel 2: fused GEMM + norms + epilogue. BM=64 tiles for 4 CTAs/SM.
// grid (16, T). 256 threads = 8 warps (2 M-strips x 4 N-strips of 32x16).
// dist = 2*qp - q_sq - p_sq
// ---------------------------------------------------------------------------
__global__ __launch_bounds__(256, 4) void dist_kernel(const float* __restrict__ query,
                                                      float* __restrict__ out) {
    const int t    = blockIdx.y;
    const int rb   = blockIdx.x;
    const int tid  = threadIdx.x;
    const int lane = tid & 31;
    const int warp = tid >> 5;
    const int warpM = warp >> 2;  // 0..1 (32-row strips)
    const int warpN = warp & 3;   // 0..3 (16-col strips)

    __shared__ __align__(16) __nv_bfloat16 sQ[BM * LDS_Q];
    __shared__ __align__(16) __nv_bfloat16 sP[WAY * LDS_P];
    __shared__ float sQsq[BM];
    __shared__ float sPsq[WAY];

    if (tid < WAY) sPsq[tid] = g_psq[t * WAY + tid];

    const float* qbase = query + ((size_t)t * WQ + (size_t)rb * BM) * C_DIM;
    const __nv_bfloat16* pbase = g_proto + (size_t)t * WAY * C_DIM;

    // Q chunk (64x64 f32): 4 threads/row, 4 float4 each
    const int qrow = tid >> 2;           // 0..63
    const int qcol = (tid & 3) * 16;     // f32 col base within BK
    // P chunk (64x64 bf16): 4 threads/row, 2 uint4 each
    const int prow = tid >> 2;           // 0..63
    const int pcol = (tid & 3) * 16;     // bf16 col within BK

    float4 qreg[4];
    uint4  preg[2];
    float  qsq = 0.f;
    float  acc[2][2][4];
#pragma unroll
    for (int mt = 0; mt < 2; mt++)
#pragma unroll
        for (int nt = 0; nt < 2; nt++)
#pragma unroll
            for (int i = 0; i < 4; i++) acc[mt][nt][i] = 0.f;

    const float* qsrc = qbase + (size_t)qrow * C_DIM + qcol;
    const __nv_bfloat16* psrc = pbase + (size_t)prow * C_DIM + pcol;

    // prefetch k-chunk 0
#pragma unroll
    for (int i = 0; i < 4; i++) qreg[i] = *(const float4*)(qsrc + i * 4);
    preg[0] = *(const uint4*)(psrc);
    preg[1] = *(const uint4*)(psrc + 8);

    for (int kk = 0; kk < NK; kk++) {
        // ---- stage registers -> smem (convert Q to bf16, accumulate q^2) ----
#pragma unroll
        for (int i = 0; i < 4; i++) {
            float4 v = qreg[i];
            qsq += v.x * v.x + v.y * v.y + v.z * v.z + v.w * v.w;
            __nv_bfloat162 lo = __floats2bfloat162_rn(v.x, v.y);
            __nv_bfloat162 hi = __floats2bfloat162_rn(v.z, v.w);
            uint2 st;
            st.x = *(const uint32_t*)&lo;
            st.y = *(const uint32_t*)&hi;
            *(uint2*)&sQ[qrow * LDS_Q + qcol + i * 4] = st;
        }
        *(uint4*)&sP[prow * LDS_P + pcol] = preg[0];
        *(uint4*)&sP[prow * LDS_P + pcol + 8] = preg[1];
        __syncthreads();

        // ---- prefetch next k-chunk ----
        if (kk < NK - 1) {
            const int k0 = (kk + 1) * BK;
#pragma unroll
            for (int i = 0; i < 4; i++) qreg[i] = *(const float4*)(qsrc + k0 + i * 4);
            preg[0] = *(const uint4*)(psrc + k0);
            preg[1] = *(const uint4*)(psrc + k0 + 8);
        }

        // ---- compute: 4 k16 steps, 2 m-tiles x 2 n-tiles of m16n8k16 ----
#pragma unroll
        for (int ks = 0; ks < 4; ks++) {
            const int col = ks * 16 + (lane & 3) * 2;
            uint32_t a[2][4], b[2][2];
#pragma unroll
            for (int mt = 0; mt < 2; mt++) {
                const int rr = warpM * 32 + mt * 16 + (lane >> 2);
                a[mt][0] = *(const uint32_t*)&sQ[rr * LDS_Q + col];
                a[mt][1] = *(const uint32_t*)&sQ[(rr + 8) * LDS_Q + col];
                a[mt][2] = *(const uint32_t*)&sQ[rr * LDS_Q + col + 8];
                a[mt][3] = *(const uint32_t*)&sQ[(rr + 8) * LDS_Q + col + 8];
            }
#pragma unroll
            for (int nt = 0; nt < 2; nt++) {
                const int n = warpN * 16 + nt * 8 + (lane >> 2);
                b[nt][0] = *(const uint32_t*)&sP[n * LDS_P + col];
                b[nt][1] = *(const uint32_t*)&sP[n * LDS_P + col + 8];
            }
#pragma unroll
            for (int mt = 0; mt < 2; mt++)
#pragma unroll
                for (int nt = 0; nt < 2; nt++)
                    mma16816(acc[mt][nt], a[mt], b[nt]);
        }
        __syncthreads();
    }

    // ---- q^2: reduce across the 4 col-chunk threads of each row ----
    {
        float v = qsq;
        v += __shfl_xor_sync(0xffffffffu, v, 1);
        v += __shfl_xor_sync(0xffffffffu, v, 2);
        if ((tid & 3) == 0) sQsq[qrow] = v;
    }
    __syncthreads();

    // ---- epilogue: dist = 2*qp - q_sq - p_sq ----
    float* obase = out + ((size_t)t * WQ + (size_t)rb * BM) * WAY;
#pragma unroll
    for (int mt = 0; mt < 2; mt++) {
        const int r0 = warpM * 32 + mt * 16 + (lane >> 2);
        const float qs0 = sQsq[r0];
        const float qs1 = sQsq[r0 + 8];
#pragma unroll
        for (int nt = 0; nt < 2; nt++) {
            const int c0 = warpN * 16 + nt * 8 + (lane & 3) * 2;
            const float ps0 = sPsq[c0];
            const float ps1 = sPsq[c0 + 1];
            float2 d0, d1;
            d0.x = 2.f * acc[mt][nt][0] - qs0 - ps0;
            d0.y = 2.f * acc[mt][nt][1] - qs0 - ps1;
            d1.x = 2.f * acc[mt][nt][2] - qs1 - ps0;
            d1.y = 2.f * acc[mt][nt][3] - qs1 - ps1;
            *(float2*)(obase + (size_t)r0 * WAY + c0) = d0;
            *(float2*)(obase + (size_t)(r0 + 8) * WAY + c0) = d1;
        }
    }
}

extern "C" void kernel_launch(void* const* d_in, const int* in_sizes, int n_in,
                              void* d_out, int out_size) {
    const float* query   = (const float*)d_in[0];   // [32, 1024, 1024]
    const float* support = (const float*)d_in[1];   // [32, 512, 1024]
    float* out = (float*)d_out;                     // [32, 1024, 64]

    proto_kernel<<<dim3(WAY, T_DIM), 256>>>(support);
    dist_kernel<<<dim3(WQ / BM, T_DIM), 256>>>(query, out);
}

// round 13
// speedup vs baseline: 1.2500x; 1.1397x over previous
#include <cuda_runtime.h>
#include <cuda_bf16.h>
#include <cstdint>

#define T_DIM 32
#define WAY 64
#define SHOT 8
#define QUERY 16
#define C_DIM 1024
#define WQ (WAY * QUERY)   // 1024

#define BM 128
#define BK 32
#define NK (C_DIM / BK)    // 32 chunks
#define LDS_Q 40           // bf16 stride = 20 words: frag LDS conflict-free
#define QTILE (BM * LDS_Q) // 5120 bf16
#define PTILE (WAY * LDS_Q)// 2560 bf16

// Scratch (no allocations allowed): proto bf16 (4 MB) + ||p||^2 fp32.
__device__ __nv_bfloat16 g_proto[T_DIM * WAY * C_DIM];
__device__ float g_psq[T_DIM * WAY];

// ---------------------------------------------------------------------------
// Kernel 1: prototypes (mean over shots) -> bf16, and p_sq (fp32 means)
// grid (WAY, T), 256 threads; each thread owns 4 contiguous columns.
// ---------------------------------------------------------------------------
__global__ __launch_bounds__(256) void proto_kernel(const float* __restrict__ support) {
    const int way = blockIdx.x;
    const int t   = blockIdx.y;
    const int tid = threadIdx.x;

    const float* base = support + ((size_t)t * WAY * SHOT + (size_t)way * SHOT) * C_DIM + tid * 4;

    float4 s = make_float4(0.f, 0.f, 0.f, 0.f);
#pragma unroll
    for (int sh = 0; sh < SHOT; sh++) {
        float4 v = *(const float4*)(base + (size_t)sh * C_DIM);
        s.x += v.x; s.y += v.y; s.z += v.z; s.w += v.w;
    }
    s.x *= 0.125f; s.y *= 0.125f; s.z *= 0.125f; s.w *= 0.125f;

    __nv_bfloat162 lo = __floats2bfloat162_rn(s.x, s.y);
    __nv_bfloat162 hi = __floats2bfloat162_rn(s.z, s.w);
    uint2 packed;
    packed.x = *(const uint32_t*)&lo;
    packed.y = *(const uint32_t*)&hi;
    *(uint2*)&g_proto[((size_t)(t * WAY + way)) * C_DIM + tid * 4] = packed;

    float ss = s.x * s.x + s.y * s.y + s.z * s.z + s.w * s.w;
#pragma unroll
    for (int off = 16; off > 0; off >>= 1)
        ss += __shfl_xor_sync(0xffffffffu, ss, off);

    __shared__ float red[8];
    if ((tid & 31) == 0) red[tid >> 5] = ss;
    __syncthreads();
    if (tid == 0) {
        float tot = 0.f;
#pragma unroll
        for (int w = 0; w < 8; w++) tot += red[w];
        g_psq[t * WAY + way] = tot;
    }
}

// ---------------------------------------------------------------------------
// mma.sync m16n8k16 bf16 -> f32
// ---------------------------------------------------------------------------
__device__ __forceinline__ void mma16816(float* d, const uint32_t* a, const uint32_t* b) {
    asm volatile(
        "mma.sync.aligned.m16n8k16.row.col.f32.bf16.bf16.f32 "
        "{%0,%1,%2,%3}, {%4,%5,%6,%7}, {%8,%9}, {%0,%1,%2,%3};\n"
        : "+f"(d[0]), "+f"(d[1]), "+f"(d[2]), "+f"(d[3])
        : "r"(a[0]), "r"(a[1]), "r"(a[2]), "r"(a[3]), "r"(b[0]), "r"(b[1]));
}

// ---------------------------------------------------------------------------
// Kernel 2: fused GEMM + norms + epilogue, double-buffered smem, BK=32.
// grid (8, T). 256 threads = 8 warps (4 M-strips x 2 N-strips of 32x32).
// Per iter: compute(buf cur) || store regs(chunk k+1)->buf cur^1 || LDG k+2.
// dist = 2*qp - q_sq - p_sq
// ---------------------------------------------------------------------------
__global__ __launch_bounds__(256, 2) void dist_kernel(const float* __restrict__ query,
                                                      float* __restrict__ out) {
    const int t    = blockIdx.y;
    const int rb   = blockIdx.x;
    const int tid  = threadIdx.x;
    const int lane = tid & 31;
    const int warp = tid >> 5;
    const int warpM = warp & 3;   // 0..3 (32-row strips)
    const int warpN = warp >> 2;  // 0..1 (32-col strips)

    __shared__ __align__(16) __nv_bfloat16 sQ[2 * QTILE];
    __shared__ __align__(16) __nv_bfloat16 sP[2 * PTILE];
    __shared__ float sQsq[BM];
    __shared__ float sPsq[WAY];

    if (tid < WAY) sPsq[tid] = g_psq[t * WAY + tid];

    const float* qbase = query + ((size_t)t * WQ + (size_t)rb * BM) * C_DIM;
    const __nv_bfloat16* pbase = g_proto + (size_t)t * WAY * C_DIM;

    // Q chunk (128x32 f32): 2 threads/row, 16 f32 (4 float4) each
    const int qrow = tid >> 1;
    const int qcol = (tid & 1) * 16;
    // P chunk (64x32 bf16): 4 threads/row, 8 bf16 (1 uint4) each
    const int prow = tid >> 2;
    const int pcol = (tid & 3) * 8;

    const float* qsrc = qbase + (size_t)qrow * C_DIM + qcol;
    const __nv_bfloat16* psrc = pbase + (size_t)prow * C_DIM + pcol;

    float4 qreg[4];
    uint4  preg;
    float  qsq = 0.f;
    float  acc[2][4][4];
#pragma unroll
    for (int mt = 0; mt < 2; mt++)
#pragma unroll
        for (int nt = 0; nt < 4; nt++)
#pragma unroll
            for (int i = 0; i < 4; i++) acc[mt][nt][i] = 0.f;

    // ---- prologue: chunk 0 -> regs -> buf0 (+q^2), chunk 1 -> regs ----
#pragma unroll
    for (int i = 0; i < 4; i++) qreg[i] = *(const float4*)(qsrc + i * 4);
    preg = *(const uint4*)(psrc);

#pragma unroll
    for (int i = 0; i < 4; i++) {
        float4 v = qreg[i];
        qsq += v.x * v.x + v.y * v.y + v.z * v.z + v.w * v.w;
        __nv_bfloat162 lo = __floats2bfloat162_rn(v.x, v.y);
        __nv_bfloat162 hi = __floats2bfloat162_rn(v.z, v.w);
        uint2 st;
        st.x = *(const uint32_t*)&lo;
        st.y = *(const uint32_t*)&hi;
        *(uint2*)&sQ[qrow * LDS_Q + qcol + i * 4] = st;
    }
    *(uint4*)&sP[prow * LDS_Q + pcol] = preg;

#pragma unroll
    for (int i = 0; i < 4; i++) qreg[i] = *(const float4*)(qsrc + BK + i * 4);
    preg = *(const uint4*)(psrc + BK);
    __syncthreads();

    int cur = 0;
    for (int kk = 0; kk < NK; kk++) {
        // ---- store chunk kk+1 (in regs) into the other buffer ----
        if (kk + 1 < NK) {
            const int alt = cur ^ 1;
#pragma unroll
            for (int i = 0; i < 4; i++) {
                float4 v = qreg[i];
                qsq += v.x * v.x + v.y * v.y + v.z * v.z + v.w * v.w;
                __nv_bfloat162 lo = __floats2bfloat162_rn(v.x, v.y);
                __nv_bfloat162 hi = __floats2bfloat162_rn(v.z, v.w);
                uint2 st;
                st.x = *(const uint32_t*)&lo;
                st.y = *(const uint32_t*)&hi;
                *(uint2*)&sQ[alt * QTILE + qrow * LDS_Q + qcol + i * 4] = st;
            }
            *(uint4*)&sP[alt * PTILE + prow * LDS_Q + pcol] = preg;
        }
        // ---- prefetch chunk kk+2 into regs ----
        if (kk + 2 < NK) {
            const int k0 = (kk + 2) * BK;
#pragma unroll
            for (int i = 0; i < 4; i++) qreg[i] = *(const float4*)(qsrc + k0 + i * 4);
            preg = *(const uint4*)(psrc + k0);
        }

        // ---- compute chunk kk from buffer cur: 2 k16 steps ----
        const __nv_bfloat16* Qs = sQ + cur * QTILE;
        const __nv_bfloat16* Ps = sP + cur * PTILE;
#pragma unroll
        for (int ks = 0; ks < 2; ks++) {
            const int col = ks * 16 + (lane & 3) * 2;
            uint32_t a[2][4], b[4][2];
#pragma unroll
            for (int mt = 0; mt < 2; mt++) {
                const int rr = warpM * 32 + mt * 16 + (lane >> 2);
                a[mt][0] = *(const uint32_t*)&Qs[rr * LDS_Q + col];
                a[mt][1] = *(const uint32_t*)&Qs[(rr + 8) * LDS_Q + col];
                a[mt][2] = *(const uint32_t*)&Qs[rr * LDS_Q + col + 8];
                a[mt][3] = *(const uint32_t*)&Qs[(rr + 8) * LDS_Q + col + 8];
            }
#pragma unroll
            for (int nt = 0; nt < 4; nt++) {
                const int n = warpN * 32 + nt * 8 + (lane >> 2);
                b[nt][0] = *(const uint32_t*)&Ps[n * LDS_Q + col];
                b[nt][1] = *(const uint32_t*)&Ps[n * LDS_Q + col + 8];
            }
#pragma unroll
            for (int mt = 0; mt < 2; mt++)
#pragma unroll
                for (int nt = 0; nt < 4; nt++)
                    mma16816(acc[mt][nt], a[mt], b[nt]);
        }
        __syncthreads();
        cur ^= 1;
    }

    // ---- q^2: each row owned by 2 threads; reduce pair and publish ----
    {
        float v = qsq;
        v += __shfl_xor_sync(0xffffffffu, v, 1);
        if ((tid & 1) == 0) sQsq[qrow] = v;
    }
    __syncthreads();

    // ---- epilogue: dist = 2*qp - q_sq - p_sq ----
    float* obase = out + ((size_t)t * WQ + (size_t)rb * BM) * WAY;
#pragma unroll
    for (int mt = 0; mt < 2; mt++) {
        const int r0 = warpM * 32 + mt * 16 + (lane >> 2);
        const float qs0 = sQsq[r0];
        const float qs1 = sQsq[r0 + 8];
#pragma unroll
        for (int nt = 0; nt < 4; nt++) {
            const int c0 = warpN * 32 + nt * 8 + (lane & 3) * 2;
            const float ps0 = sPsq[c0];
            const float ps1 = sPsq[c0 + 1];
            float2 d0, d1;
            d0.x = 2.f * acc[mt][nt][0] - qs0 - ps0;
            d0.y = 2.f * acc[mt][nt][1] - qs0 - ps1;
            d1.x = 2.f * acc[mt][nt][2] - qs1 - ps0;
            d1.y = 2.f * acc[mt][nt][3] - qs1 - ps1;
            *(float2*)(obase + (size_t)r0 * WAY + c0) = d0;
            *(float2*)(obase + (size_t)(r0 + 8) * WAY + c0) = d1;
        }
    }
}

extern "C" void kernel_launch(void* const* d_in, const int* in_sizes, int n_in,
                              void* d_out, int out_size) {
    const float* query   = (const float*)d_in[0];   // [32, 1024, 1024]
    const float* support = (const float*)d_in[1];   // [32, 512, 1024]
    float* out = (float*)d_out;                     // [32, 1024, 64]

    proto_kernel<<<dim3(WAY, T_DIM), 256>>>(support);
    dist_kernel<<<dim3(WQ / BM, T_DIM), 256>>>(query, out);
}